// round 1
// baseline (speedup 1.0000x reference)
#include <cuda_runtime.h>
#include <math.h>

#define N_NODES 100000
#define N_EDGES 1600000
#define F_IN 64
#define HDIM 200
#define N_GRAPHS 512
#define BN_EPS 1e-5f

// ---------------- scratch (device globals; no allocation allowed) ----------------
__device__ int g_deg[N_NODES];
__device__ int g_excl[N_NODES];
__device__ int g_bsum[128];
__device__ int g_rowptr[N_NODES + 1];
__device__ int g_cnt[N_NODES];
__device__ int g_csrsrc[N_EDGES];
__device__ int g_bounds[N_GRAPHS + 1];
__device__ float g_hin1[(size_t)N_NODES * F_IN];
__device__ float g_t[(size_t)N_NODES * HDIM];
__device__ float g_h1[(size_t)N_NODES * HDIM];
__device__ float g_hin2[(size_t)N_NODES * HDIM];
__device__ float g_h2[(size_t)N_NODES * HDIM];
__device__ float g_pooled[N_GRAPHS * 2 * HDIM];

// ---------------- CSR build ----------------
__global__ void zero_deg_kernel() {
    int i = blockIdx.x * blockDim.x + threadIdx.x;
    if (i < N_NODES) g_deg[i] = 0;
}

__global__ void hist_kernel(const int* __restrict__ dst) {
    int e = blockIdx.x * blockDim.x + threadIdx.x;
    if (e < N_EDGES) atomicAdd(&g_deg[dst[e]], 1);
}

__global__ void scan_block_kernel() {
    __shared__ int sh[1024];
    int i = blockIdx.x * 1024 + threadIdx.x;
    int v = (i < N_NODES) ? g_deg[i] : 0;
    sh[threadIdx.x] = v;
    __syncthreads();
    for (int off = 1; off < 1024; off <<= 1) {
        int t = (threadIdx.x >= off) ? sh[threadIdx.x - off] : 0;
        __syncthreads();
        sh[threadIdx.x] += t;
        __syncthreads();
    }
    if (i < N_NODES) g_excl[i] = sh[threadIdx.x] - v;
    if (threadIdx.x == 1023) g_bsum[blockIdx.x] = sh[1023];
}

__global__ void scan_sums_kernel(int nb) {
    if (threadIdx.x == 0 && blockIdx.x == 0) {
        int run = 0;
        for (int b = 0; b < nb; b++) { int t = g_bsum[b]; g_bsum[b] = run; run += t; }
    }
}

__global__ void scan_finish_kernel() {
    int i = blockIdx.x * blockDim.x + threadIdx.x;
    if (i < N_NODES) {
        int v = g_excl[i] + g_bsum[i >> 10];
        g_rowptr[i] = v;
        g_cnt[i] = v;
    }
    if (i == 0) g_rowptr[N_NODES] = N_EDGES;
}

__global__ void fill_kernel(const int* __restrict__ src, const int* __restrict__ dst) {
    int e = blockIdx.x * blockDim.x + threadIdx.x;
    if (e < N_EDGES) {
        int d = dst[e];
        int p = atomicAdd(&g_cnt[d], 1);
        g_csrsrc[p] = src[e];
    }
}

// ---------------- GIN aggregation: h_in[i] = (1+eps)*x[i] + sum_{j in N(i)} x[j] ----------------
template <int F, int PL>
__global__ void agg_kernel(const float* __restrict__ X, const float* __restrict__ epsp,
                           float* __restrict__ out) {
    int w = (blockIdx.x * blockDim.x + threadIdx.x) >> 5;
    int lane = threadIdx.x & 31;
    if (w >= N_NODES) return;
    float acc[PL];
#pragma unroll
    for (int j = 0; j < PL; j++) acc[j] = 0.f;
    int beg = g_rowptr[w], end = g_rowptr[w + 1];
    for (int e = beg; e < end; e++) {
        int s = g_csrsrc[e];
        const float* xs = X + (size_t)s * F;
#pragma unroll
        for (int j = 0; j < PL; j++) {
            int c = lane + j * 32;
            if (c < F) acc[j] += __ldg(xs + c);
        }
    }
    float ep = 1.f + *epsp;
    const float* xi = X + (size_t)w * F;
    float* o = out + (size_t)w * F;
#pragma unroll
    for (int j = 0; j < PL; j++) {
        int c = lane + j * 32;
        if (c < F) o[c] = ep * xi[c] + acc[j];
    }
}

// ---------------- SGEMM: C[M,N] = epi(A[M,K] @ B[K,N]) ----------------
// EPI 0: relu(acc + bias)
// EPI 1: bn(relu(acc + bias))  (eval-mode batchnorm)
template <int EPI>
__global__ __launch_bounds__(256) void sgemm_kernel(
    const float* __restrict__ A, const float* __restrict__ B,
    const float* __restrict__ bias,
    const float* __restrict__ gamma, const float* __restrict__ beta,
    const float* __restrict__ mean, const float* __restrict__ var,
    float* __restrict__ C, int M, int K, int N) {
    const int BM = 128, BN = 128, BK = 8, TM = 8, TN = 8;
    __shared__ float As[BK][BM];
    __shared__ float Bs[BK][BN];
    int tid = threadIdx.x;
    int row0 = blockIdx.x * BM, col0 = blockIdx.y * BN;
    int tx = tid % 16, ty = tid / 16;

    float acc[TM][TN];
#pragma unroll
    for (int i = 0; i < TM; i++)
#pragma unroll
        for (int j = 0; j < TN; j++) acc[i][j] = 0.f;

    int a_row = tid >> 1, a_col = (tid & 1) * 4;
    int b_row = tid >> 5, b_col = (tid & 31) * 4;
    bool a_ok = (row0 + a_row) < M;
    const float* Aptr = A + (size_t)(row0 + a_row) * K + a_col;

    for (int k0 = 0; k0 < K; k0 += BK) {
        float4 av = make_float4(0.f, 0.f, 0.f, 0.f);
        if (a_ok) av = *(const float4*)(Aptr + k0);
        As[a_col + 0][a_row] = av.x;
        As[a_col + 1][a_row] = av.y;
        As[a_col + 2][a_row] = av.z;
        As[a_col + 3][a_row] = av.w;

        float4 bv = make_float4(0.f, 0.f, 0.f, 0.f);
        if (col0 + b_col < N)  // N % 4 == 0, cols aligned -> full-vector guard ok
            bv = *(const float4*)(B + (size_t)(k0 + b_row) * N + col0 + b_col);
        *(float4*)&Bs[b_row][b_col] = bv;
        __syncthreads();

#pragma unroll
        for (int k = 0; k < BK; k++) {
            float a[TM], b[TN];
            *(float4*)&a[0] = *(const float4*)&As[k][ty * TM];
            *(float4*)&a[4] = *(const float4*)&As[k][ty * TM + 4];
            *(float4*)&b[0] = *(const float4*)&Bs[k][tx * TN];
            *(float4*)&b[4] = *(const float4*)&Bs[k][tx * TN + 4];
#pragma unroll
            for (int i = 0; i < TM; i++)
#pragma unroll
                for (int j = 0; j < TN; j++) acc[i][j] += a[i] * b[j];
        }
        __syncthreads();
    }

#pragma unroll
    for (int i = 0; i < TM; i++) {
        int r = row0 + ty * TM + i;
        if (r >= M) continue;
        float* crow = C + (size_t)r * N;
#pragma unroll
        for (int j = 0; j < TN; j++) {
            int c = col0 + tx * TN + j;
            if (c >= N) continue;
            float v = acc[i][j] + bias[c];
            v = fmaxf(v, 0.f);
            if (EPI == 1) {
                v = (v - mean[c]) * rsqrtf(var[c] + BN_EPS) * gamma[c] + beta[c];
            }
            crow[c] = v;
        }
    }
}

// ---------------- pooling ----------------
__global__ void graph_bounds_kernel(const int* __restrict__ batch) {
    int g = blockIdx.x * blockDim.x + threadIdx.x;
    if (g > N_GRAPHS) return;
    int lo = 0, hi = N_NODES;
    while (lo < hi) {
        int mid = (lo + hi) >> 1;
        if (batch[mid] < g) lo = mid + 1; else hi = mid;
    }
    g_bounds[g] = lo;
}

__global__ void pool_kernel() {
    int g = blockIdx.x;
    int f = threadIdx.x;
    if (f >= HDIM) return;
    int beg = g_bounds[g], end = g_bounds[g + 1];
    float s = 0.f, m = -INFINITY;
    for (int i = beg; i < end; i++) {
        float v = g_h2[(size_t)i * HDIM + f];
        s += v;
        m = fmaxf(m, v);
    }
    g_pooled[g * (2 * HDIM) + f] = s;
    g_pooled[g * (2 * HDIM) + HDIM + f] = m;
}

// ---------------- FC + log_softmax ----------------
__global__ void fc_kernel(const float* __restrict__ Wfc, const float* __restrict__ bfc,
                          float* __restrict__ out) {
    int w = (blockIdx.x * blockDim.x + threadIdx.x) >> 5;
    int lane = threadIdx.x & 31;
    if (w >= N_GRAPHS) return;
    float l0 = 0.f, l1 = 0.f;
    const float* p = &g_pooled[w * (2 * HDIM)];
    for (int k = lane; k < 2 * HDIM; k += 32) {
        float pv = p[k];
        l0 += pv * Wfc[k * 2 + 0];
        l1 += pv * Wfc[k * 2 + 1];
    }
#pragma unroll
    for (int off = 16; off; off >>= 1) {
        l0 += __shfl_down_sync(0xFFFFFFFFu, l0, off);
        l1 += __shfl_down_sync(0xFFFFFFFFu, l1, off);
    }
    if (lane == 0) {
        l0 += bfc[0];
        l1 += bfc[1];
        float m = fmaxf(l0, l1);
        float lse = m + logf(expf(l0 - m) + expf(l1 - m));
        out[w * 2 + 0] = l0 - lse;
        out[w * 2 + 1] = l1 - lse;
    }
}

// ---------------- launch ----------------
extern "C" void kernel_launch(void* const* d_in, const int* in_sizes, int n_in,
                              void* d_out, int out_size) {
    const float* x    = (const float*)d_in[0];
    const int*   ei   = (const int*)d_in[1];
    const int*   batch = (const int*)d_in[2];
    const float* eps1 = (const float*)d_in[3];
    const float* W1a  = (const float*)d_in[4];
    const float* b1a  = (const float*)d_in[5];
    const float* W1b  = (const float*)d_in[6];
    const float* b1b  = (const float*)d_in[7];
    const float* bn1g = (const float*)d_in[8];
    const float* bn1b = (const float*)d_in[9];
    const float* bn1m = (const float*)d_in[10];
    const float* bn1v = (const float*)d_in[11];
    const float* eps2 = (const float*)d_in[12];
    const float* W2a  = (const float*)d_in[13];
    const float* b2a  = (const float*)d_in[14];
    const float* W2b  = (const float*)d_in[15];
    const float* b2b  = (const float*)d_in[16];
    const float* bn2g = (const float*)d_in[17];
    const float* bn2b = (const float*)d_in[18];
    const float* bn2m = (const float*)d_in[19];
    const float* bn2v = (const float*)d_in[20];
    const float* Wfc  = (const float*)d_in[21];
    const float* bfc  = (const float*)d_in[22];
    float* out = (float*)d_out;

    const int* src = ei;
    const int* dst = ei + N_EDGES;

    float *hin1, *t, *h1, *hin2, *h2;
    cudaGetSymbolAddress((void**)&hin1, g_hin1);
    cudaGetSymbolAddress((void**)&t,    g_t);
    cudaGetSymbolAddress((void**)&h1,   g_h1);
    cudaGetSymbolAddress((void**)&hin2, g_hin2);
    cudaGetSymbolAddress((void**)&h2,   g_h2);

    const int TPB = 256;
    int nbNodes = (N_NODES + TPB - 1) / TPB;      // 391
    int nbEdges = (N_EDGES + TPB - 1) / TPB;      // 6250
    int nbScan  = (N_NODES + 1023) / 1024;        // 98
    int nbWarpNodes = (N_NODES * 32 + TPB - 1) / TPB;  // 12500

    // CSR build (reused by both layers)
    zero_deg_kernel<<<nbNodes, TPB>>>();
    hist_kernel<<<nbEdges, TPB>>>(dst);
    scan_block_kernel<<<nbScan, 1024>>>();
    scan_sums_kernel<<<1, 32>>>(nbScan);
    scan_finish_kernel<<<nbNodes, TPB>>>();
    fill_kernel<<<nbEdges, TPB>>>(src, dst);

    dim3 gemm_grid((N_NODES + 127) / 128, (HDIM + 127) / 128);  // 782 x 2

    // Layer 1
    agg_kernel<F_IN, 2><<<nbWarpNodes, TPB>>>(x, eps1, hin1);
    sgemm_kernel<0><<<gemm_grid, 256>>>(hin1, W1a, b1a, nullptr, nullptr, nullptr, nullptr,
                                        t, N_NODES, F_IN, HDIM);
    sgemm_kernel<1><<<gemm_grid, 256>>>(t, W1b, b1b, bn1g, bn1b, bn1m, bn1v,
                                        h1, N_NODES, HDIM, HDIM);

    // Layer 2
    agg_kernel<HDIM, 7><<<nbWarpNodes, TPB>>>(h1, eps2, hin2);
    sgemm_kernel<0><<<gemm_grid, 256>>>(hin2, W2a, b2a, nullptr, nullptr, nullptr, nullptr,
                                        t, N_NODES, HDIM, HDIM);
    sgemm_kernel<1><<<gemm_grid, 256>>>(t, W2b, b2b, bn2g, bn2b, bn2m, bn2v,
                                        h2, N_NODES, HDIM, HDIM);

    // Pooling + FC + log_softmax
    graph_bounds_kernel<<<3, 256>>>(batch);
    pool_kernel<<<N_GRAPHS, 256>>>();
    fc_kernel<<<(N_GRAPHS * 32 + TPB - 1) / TPB, TPB>>>(Wfc, bfc, out);
}

// round 2
// speedup vs baseline: 1.9238x; 1.9238x over previous
#include <cuda_runtime.h>
#include <math.h>
#include <stdint.h>

#define N_NODES 100000
#define N_EDGES 1600000
#define F_IN 64
#define HDIM 200
#define N_GRAPHS 512
#define BN_EPS 1e-5f

// ---------------- scratch (device globals; no allocation allowed) ----------------
__device__ int g_deg[N_NODES];
__device__ int g_excl[N_NODES];
__device__ int g_bsum[128];
__device__ int g_rowptr[N_NODES + 1];
__device__ int g_cnt[N_NODES];
__device__ int g_csrsrc[N_EDGES];
__device__ int g_bounds[N_GRAPHS + 1];
__device__ float g_hin1[(size_t)N_NODES * F_IN];
__device__ float g_t[(size_t)N_NODES * HDIM];
__device__ float g_h1[(size_t)N_NODES * HDIM];
__device__ float g_hin2[(size_t)N_NODES * HDIM];
__device__ float g_h2[(size_t)N_NODES * HDIM];
__device__ float g_pooled[N_GRAPHS * 2 * HDIM];

// ---------------- CSR build ----------------
__global__ void zero_deg_kernel() {
    int i = blockIdx.x * blockDim.x + threadIdx.x;
    if (i < N_NODES) g_deg[i] = 0;
}

__global__ void hist_kernel(const int* __restrict__ dst) {
    int e = blockIdx.x * blockDim.x + threadIdx.x;
    if (e < N_EDGES) atomicAdd(&g_deg[dst[e]], 1);
}

__global__ void scan_block_kernel() {
    __shared__ int sh[1024];
    int i = blockIdx.x * 1024 + threadIdx.x;
    int v = (i < N_NODES) ? g_deg[i] : 0;
    sh[threadIdx.x] = v;
    __syncthreads();
    for (int off = 1; off < 1024; off <<= 1) {
        int t = (threadIdx.x >= off) ? sh[threadIdx.x - off] : 0;
        __syncthreads();
        sh[threadIdx.x] += t;
        __syncthreads();
    }
    if (i < N_NODES) g_excl[i] = sh[threadIdx.x] - v;
    if (threadIdx.x == 1023) g_bsum[blockIdx.x] = sh[1023];
}

__global__ void scan_sums_kernel(int nb) {
    if (threadIdx.x == 0 && blockIdx.x == 0) {
        int run = 0;
        for (int b = 0; b < nb; b++) { int t = g_bsum[b]; g_bsum[b] = run; run += t; }
    }
}

__global__ void scan_finish_kernel() {
    int i = blockIdx.x * blockDim.x + threadIdx.x;
    if (i < N_NODES) {
        int v = g_excl[i] + g_bsum[i >> 10];
        g_rowptr[i] = v;
        g_cnt[i] = v;
    }
    if (i == 0) g_rowptr[N_NODES] = N_EDGES;
}

__global__ void fill_kernel(const int* __restrict__ src, const int* __restrict__ dst) {
    int e = blockIdx.x * blockDim.x + threadIdx.x;
    if (e < N_EDGES) {
        int d = dst[e];
        int p = atomicAdd(&g_cnt[d], 1);
        g_csrsrc[p] = src[e];
    }
}

// ---------------- GIN aggregation: h_in[i] = (1+eps)*x[i] + sum_{j in N(i)} x[j] ----------
// F=64: warp per node, one float2 per lane (exactly 64 floats)
__global__ void agg64_kernel(const float* __restrict__ X, const float* __restrict__ epsp,
                             float* __restrict__ out) {
    int w = (blockIdx.x * blockDim.x + threadIdx.x) >> 5;
    int lane = threadIdx.x & 31;
    if (w >= N_NODES) return;
    float2 acc = make_float2(0.f, 0.f);
    int beg = g_rowptr[w], end = g_rowptr[w + 1];
    for (int e = beg; e < end; e++) {
        int s = g_csrsrc[e];
        float2 v = __ldg((const float2*)(X + (size_t)s * F_IN) + lane);
        acc.x += v.x; acc.y += v.y;
    }
    float ep = 1.f + *epsp;
    float2 xi = *((const float2*)(X + (size_t)w * F_IN) + lane);
    float2 o;
    o.x = ep * xi.x + acc.x;
    o.y = ep * xi.y + acc.y;
    *((float2*)(out + (size_t)w * F_IN) + lane) = o;
}

// F=200: warp per node, 50 float4 per row => lane gets idx lane, and lane+32 (lane<18)
__global__ void agg200_kernel(const float* __restrict__ X, const float* __restrict__ epsp,
                              float* __restrict__ out) {
    int w = (blockIdx.x * blockDim.x + threadIdx.x) >> 5;
    int lane = threadIdx.x & 31;
    if (w >= N_NODES) return;
    float4 a0 = make_float4(0.f, 0.f, 0.f, 0.f);
    float4 a1 = make_float4(0.f, 0.f, 0.f, 0.f);
    bool has2 = lane < 18;
    int beg = g_rowptr[w], end = g_rowptr[w + 1];
    for (int e = beg; e < end; e++) {
        int s = g_csrsrc[e];
        const float4* xs = (const float4*)(X + (size_t)s * HDIM);
        float4 v0 = __ldg(xs + lane);
        a0.x += v0.x; a0.y += v0.y; a0.z += v0.z; a0.w += v0.w;
        if (has2) {
            float4 v1 = __ldg(xs + lane + 32);
            a1.x += v1.x; a1.y += v1.y; a1.z += v1.z; a1.w += v1.w;
        }
    }
    float ep = 1.f + *epsp;
    const float4* xi = (const float4*)(X + (size_t)w * HDIM);
    float4* o = (float4*)(out + (size_t)w * HDIM);
    float4 x0 = xi[lane];
    float4 r0;
    r0.x = ep * x0.x + a0.x; r0.y = ep * x0.y + a0.y;
    r0.z = ep * x0.z + a0.z; r0.w = ep * x0.w + a0.w;
    o[lane] = r0;
    if (has2) {
        float4 x1 = xi[lane + 32];
        float4 r1;
        r1.x = ep * x1.x + a1.x; r1.y = ep * x1.y + a1.y;
        r1.z = ep * x1.z + a1.z; r1.w = ep * x1.w + a1.w;
        o[lane + 32] = r1;
    }
}

// ---------------- tensor-core TF32 GEMM: C[M,N] = epi(A[M,K] @ B[K,N]) ----------------
__device__ __forceinline__ uint32_t f2tf32(float f) {
    uint32_t u;
    asm("cvt.rna.tf32.f32 %0, %1;" : "=r"(u) : "f"(f));
    return u;
}

__device__ __forceinline__ void mma_tf32(float* c, uint32_t a0, uint32_t a1,
                                         uint32_t a2, uint32_t a3,
                                         uint32_t b0, uint32_t b1) {
    asm volatile(
        "mma.sync.aligned.m16n8k8.row.col.f32.tf32.tf32.f32 "
        "{%0,%1,%2,%3}, {%4,%5,%6,%7}, {%8,%9}, {%0,%1,%2,%3};"
        : "+f"(c[0]), "+f"(c[1]), "+f"(c[2]), "+f"(c[3])
        : "r"(a0), "r"(a1), "r"(a2), "r"(a3), "r"(b0), "r"(b1));
}

// EPI 0: relu(acc + bias)
// EPI 1: bn(relu(acc + bias))  (eval-mode batchnorm)
template <int EPI>
__global__ __launch_bounds__(256) void gemm_tc_kernel(
    const float* __restrict__ A, const float* __restrict__ B,
    const float* __restrict__ bias,
    const float* __restrict__ gamma, const float* __restrict__ beta,
    const float* __restrict__ mean, const float* __restrict__ var,
    float* __restrict__ C, int M, int K, int N) {
    const int BM = 128, BN = 128, BK = 16;
    __shared__ uint32_t As[BM][BK + 4];   // stride 20: frag loads conflict-free
    __shared__ uint32_t Bs[BK][BN + 8];   // stride 136 (== 8 mod 32): conflict-free

    int tid = threadIdx.x;
    int lane = tid & 31, wid = tid >> 5;
    int warp_m = wid & 3, warp_n = wid >> 2;    // 4 x 2 warp grid, warp tile 32x64
    int row0 = blockIdx.x * BM, col0 = blockIdx.y * BN;
    int g = lane >> 2, t4 = lane & 3;

    float acc[2][8][4];
#pragma unroll
    for (int mt = 0; mt < 2; mt++)
#pragma unroll
        for (int nt = 0; nt < 8; nt++)
#pragma unroll
            for (int i = 0; i < 4; i++) acc[mt][nt][i] = 0.f;

    // loader assignments
    int la_m = tid >> 1;            // 0..127
    int la_k = (tid & 1) * 8;       // 0 or 8
    int lb_k = tid >> 4;            // 0..15
    int lb_n = (tid & 15) * 8;      // 0..120
    int ar = row0 + la_m;
    bool a_row_ok = ar < M;

    int nk = (K + BK - 1) / BK;
    for (int kt = 0; kt < nk; kt++) {
        // load A tile
#pragma unroll
        for (int v = 0; v < 2; v++) {
            int kg = kt * BK + la_k + v * 4;
            float4 av = make_float4(0.f, 0.f, 0.f, 0.f);
            if (a_row_ok && kg < K)
                av = *(const float4*)(A + (size_t)ar * K + kg);
            As[la_m][la_k + v * 4 + 0] = f2tf32(av.x);
            As[la_m][la_k + v * 4 + 1] = f2tf32(av.y);
            As[la_m][la_k + v * 4 + 2] = f2tf32(av.z);
            As[la_m][la_k + v * 4 + 3] = f2tf32(av.w);
        }
        // load B tile
        int bk = kt * BK + lb_k;
#pragma unroll
        for (int v = 0; v < 2; v++) {
            int cg = col0 + lb_n + v * 4;
            float4 bv = make_float4(0.f, 0.f, 0.f, 0.f);
            if (bk < K && cg < N)
                bv = *(const float4*)(B + (size_t)bk * N + cg);
            Bs[lb_k][lb_n + v * 4 + 0] = f2tf32(bv.x);
            Bs[lb_k][lb_n + v * 4 + 1] = f2tf32(bv.y);
            Bs[lb_k][lb_n + v * 4 + 2] = f2tf32(bv.z);
            Bs[lb_k][lb_n + v * 4 + 3] = f2tf32(bv.w);
        }
        __syncthreads();

#pragma unroll
        for (int k8 = 0; k8 < 2; k8++) {
            int kb = k8 * 8;
            uint32_t a[2][4];
#pragma unroll
            for (int mt = 0; mt < 2; mt++) {
                int r = warp_m * 32 + mt * 16 + g;
                a[mt][0] = As[r][kb + t4];
                a[mt][1] = As[r + 8][kb + t4];
                a[mt][2] = As[r][kb + t4 + 4];
                a[mt][3] = As[r + 8][kb + t4 + 4];
            }
#pragma unroll
            for (int nt = 0; nt < 8; nt++) {
                int cidx = warp_n * 64 + nt * 8 + g;
                uint32_t b0 = Bs[kb + t4][cidx];
                uint32_t b1 = Bs[kb + t4 + 4][cidx];
                mma_tf32(acc[0][nt], a[0][0], a[0][1], a[0][2], a[0][3], b0, b1);
                mma_tf32(acc[1][nt], a[1][0], a[1][1], a[1][2], a[1][3], b0, b1);
            }
        }
        __syncthreads();
    }

    // epilogue: C layout per mma: c0:(g, 2*t4) c1:(g, 2*t4+1) c2:(g+8, 2*t4) c3:(g+8, 2*t4+1)
#pragma unroll
    for (int nt = 0; nt < 8; nt++) {
        int col = col0 + warp_n * 64 + nt * 8 + 2 * t4;   // even; N even -> col<N implies col+1<N
        if (col >= N) continue;
        float bi0 = bias[col], bi1 = bias[col + 1];
        float s0 = 1.f, s1 = 1.f, o0 = 0.f, o1 = 0.f;
        if (EPI == 1) {
            s0 = rsqrtf(var[col] + BN_EPS) * gamma[col];
            s1 = rsqrtf(var[col + 1] + BN_EPS) * gamma[col + 1];
            o0 = beta[col] - mean[col] * s0;
            o1 = beta[col + 1] - mean[col + 1] * s1;
        }
#pragma unroll
        for (int mt = 0; mt < 2; mt++) {
#pragma unroll
            for (int h = 0; h < 2; h++) {
                int r = row0 + warp_m * 32 + mt * 16 + g + h * 8;
                if (r >= M) continue;
                float v0 = fmaxf(acc[mt][nt][2 * h + 0] + bi0, 0.f);
                float v1 = fmaxf(acc[mt][nt][2 * h + 1] + bi1, 0.f);
                if (EPI == 1) { v0 = v0 * s0 + o0; v1 = v1 * s1 + o1; }
                *(float2*)(C + (size_t)r * N + col) = make_float2(v0, v1);
            }
        }
    }
}

// ---------------- pooling ----------------
__global__ void graph_bounds_kernel(const int* __restrict__ batch) {
    int g = blockIdx.x * blockDim.x + threadIdx.x;
    if (g > N_GRAPHS) return;
    int lo = 0, hi = N_NODES;
    while (lo < hi) {
        int mid = (lo + hi) >> 1;
        if (batch[mid] < g) lo = mid + 1; else hi = mid;
    }
    g_bounds[g] = lo;
}

__global__ void pool_kernel() {
    int g = blockIdx.x;
    int f = threadIdx.x;
    if (f >= HDIM) return;
    int beg = g_bounds[g], end = g_bounds[g + 1];
    float s = 0.f, m = -INFINITY;
    for (int i = beg; i < end; i++) {
        float v = g_h2[(size_t)i * HDIM + f];
        s += v;
        m = fmaxf(m, v);
    }
    g_pooled[g * (2 * HDIM) + f] = s;
    g_pooled[g * (2 * HDIM) + HDIM + f] = m;
}

// ---------------- FC + log_softmax ----------------
__global__ void fc_kernel(const float* __restrict__ Wfc, const float* __restrict__ bfc,
                          float* __restrict__ out) {
    int w = (blockIdx.x * blockDim.x + threadIdx.x) >> 5;
    int lane = threadIdx.x & 31;
    if (w >= N_GRAPHS) return;
    float l0 = 0.f, l1 = 0.f;
    const float* p = &g_pooled[w * (2 * HDIM)];
    for (int k = lane; k < 2 * HDIM; k += 32) {
        float pv = p[k];
        l0 += pv * Wfc[k * 2 + 0];
        l1 += pv * Wfc[k * 2 + 1];
    }
#pragma unroll
    for (int off = 16; off; off >>= 1) {
        l0 += __shfl_down_sync(0xFFFFFFFFu, l0, off);
        l1 += __shfl_down_sync(0xFFFFFFFFu, l1, off);
    }
    if (lane == 0) {
        l0 += bfc[0];
        l1 += bfc[1];
        float m = fmaxf(l0, l1);
        float lse = m + logf(expf(l0 - m) + expf(l1 - m));
        out[w * 2 + 0] = l0 - lse;
        out[w * 2 + 1] = l1 - lse;
    }
}

// ---------------- launch ----------------
extern "C" void kernel_launch(void* const* d_in, const int* in_sizes, int n_in,
                              void* d_out, int out_size) {
    const float* x    = (const float*)d_in[0];
    const int*   ei   = (const int*)d_in[1];
    const int*   batch = (const int*)d_in[2];
    const float* eps1 = (const float*)d_in[3];
    const float* W1a  = (const float*)d_in[4];
    const float* b1a  = (const float*)d_in[5];
    const float* W1b  = (const float*)d_in[6];
    const float* b1b  = (const float*)d_in[7];
    const float* bn1g = (const float*)d_in[8];
    const float* bn1b = (const float*)d_in[9];
    const float* bn1m = (const float*)d_in[10];
    const float* bn1v = (const float*)d_in[11];
    const float* eps2 = (const float*)d_in[12];
    const float* W2a  = (const float*)d_in[13];
    const float* b2a  = (const float*)d_in[14];
    const float* W2b  = (const float*)d_in[15];
    const float* b2b  = (const float*)d_in[16];
    const float* bn2g = (const float*)d_in[17];
    const float* bn2b = (const float*)d_in[18];
    const float* bn2m = (const float*)d_in[19];
    const float* bn2v = (const float*)d_in[20];
    const float* Wfc  = (const float*)d_in[21];
    const float* bfc  = (const float*)d_in[22];
    float* out = (float*)d_out;

    const int* src = ei;
    const int* dst = ei + N_EDGES;

    float *hin1, *t, *h1, *hin2, *h2;
    cudaGetSymbolAddress((void**)&hin1, g_hin1);
    cudaGetSymbolAddress((void**)&t,    g_t);
    cudaGetSymbolAddress((void**)&h1,   g_h1);
    cudaGetSymbolAddress((void**)&hin2, g_hin2);
    cudaGetSymbolAddress((void**)&h2,   g_h2);

    const int TPB = 256;
    int nbNodes = (N_NODES + TPB - 1) / TPB;
    int nbEdges = (N_EDGES + TPB - 1) / TPB;
    int nbScan  = (N_NODES + 1023) / 1024;
    int nbWarpNodes = (N_NODES * 32 + TPB - 1) / TPB;

    // CSR build (reused by both layers)
    zero_deg_kernel<<<nbNodes, TPB>>>();
    hist_kernel<<<nbEdges, TPB>>>(dst);
    scan_block_kernel<<<nbScan, 1024>>>();
    scan_sums_kernel<<<1, 32>>>(nbScan);
    scan_finish_kernel<<<nbNodes, TPB>>>();
    fill_kernel<<<nbEdges, TPB>>>(src, dst);

    dim3 gemm_grid((N_NODES + 127) / 128, (HDIM + 127) / 128);  // 782 x 2

    // Layer 1
    agg64_kernel<<<nbWarpNodes, TPB>>>(x, eps1, hin1);
    gemm_tc_kernel<0><<<gemm_grid, 256>>>(hin1, W1a, b1a, nullptr, nullptr, nullptr, nullptr,
                                          t, N_NODES, F_IN, HDIM);
    gemm_tc_kernel<1><<<gemm_grid, 256>>>(t, W1b, b1b, bn1g, bn1b, bn1m, bn1v,
                                          h1, N_NODES, HDIM, HDIM);

    // Layer 2
    agg200_kernel<<<nbWarpNodes, TPB>>>(h1, eps2, hin2);
    gemm_tc_kernel<0><<<gemm_grid, 256>>>(hin2, W2a, b2a, nullptr, nullptr, nullptr, nullptr,
                                          t, N_NODES, HDIM, HDIM);
    gemm_tc_kernel<1><<<gemm_grid, 256>>>(t, W2b, b2b, bn2g, bn2b, bn2m, bn2v,
                                          h2, N_NODES, HDIM, HDIM);

    // Pooling + FC + log_softmax
    graph_bounds_kernel<<<3, 256>>>(batch);
    pool_kernel<<<N_GRAPHS, 256>>>();
    fc_kernel<<<(N_GRAPHS * 32 + TPB - 1) / TPB, TPB>>>(Wfc, bfc, out);
}

// round 3
// speedup vs baseline: 3.6222x; 1.8829x over previous
#include <cuda_runtime.h>
#include <cuda_bf16.h>
#include <math.h>
#include <stdint.h>

#define N_NODES 100000
#define N_EDGES 1600000
#define F_IN 64
#define HDIM 200
#define N_GRAPHS 512
#define BN_EPS 1e-5f

// ---------------- scratch (device globals; no allocation allowed) ----------------
__device__ int g_deg[N_NODES];
__device__ int g_excl[N_NODES];
__device__ int g_bsum[128];
__device__ int g_rowptr[N_NODES + 1];
__device__ int g_cnt[N_NODES];
__device__ int g_csrsrc[N_EDGES];
__device__ int g_bounds[N_GRAPHS + 1];

__device__ __nv_bfloat16 g_xb[(size_t)N_NODES * F_IN];
__device__ __nv_bfloat16 g_hin1[(size_t)N_NODES * F_IN];
__device__ __nv_bfloat16 g_tb[(size_t)N_NODES * HDIM];
__device__ __nv_bfloat16 g_h1[(size_t)N_NODES * HDIM];
__device__ __nv_bfloat16 g_hin2[(size_t)N_NODES * HDIM];
__device__ float g_h2[(size_t)N_NODES * HDIM];
__device__ float g_pooled[N_GRAPHS * 2 * HDIM];
__device__ __nv_bfloat16 g_w1a[F_IN * HDIM];
__device__ __nv_bfloat16 g_w1b[HDIM * HDIM];
__device__ __nv_bfloat16 g_w2a[HDIM * HDIM];
__device__ __nv_bfloat16 g_w2b[HDIM * HDIM];

// ---------------- fp32 -> bf16 convert ----------------
__global__ void convf2b_kernel(const float* __restrict__ s, __nv_bfloat16* __restrict__ d, int n) {
    int i = blockIdx.x * blockDim.x + threadIdx.x;
    if (i < n) d[i] = __float2bfloat16(s[i]);
}

// ---------------- CSR build ----------------
__global__ void zero_deg_kernel() {
    int i = blockIdx.x * blockDim.x + threadIdx.x;
    if (i < N_NODES) g_deg[i] = 0;
}

__global__ void hist_kernel(const int* __restrict__ dst) {
    int e = blockIdx.x * blockDim.x + threadIdx.x;
    if (e < N_EDGES) atomicAdd(&g_deg[dst[e]], 1);
}

__global__ void scan_block_kernel() {
    __shared__ int sh[1024];
    int i = blockIdx.x * 1024 + threadIdx.x;
    int v = (i < N_NODES) ? g_deg[i] : 0;
    sh[threadIdx.x] = v;
    __syncthreads();
    for (int off = 1; off < 1024; off <<= 1) {
        int t = (threadIdx.x >= off) ? sh[threadIdx.x - off] : 0;
        __syncthreads();
        sh[threadIdx.x] += t;
        __syncthreads();
    }
    if (i < N_NODES) g_excl[i] = sh[threadIdx.x] - v;
    if (threadIdx.x == 1023) g_bsum[blockIdx.x] = sh[1023];
}

__global__ void scan_sums_kernel(int nb) {
    if (threadIdx.x == 0 && blockIdx.x == 0) {
        int run = 0;
        for (int b = 0; b < nb; b++) { int t = g_bsum[b]; g_bsum[b] = run; run += t; }
    }
}

__global__ void scan_finish_kernel() {
    int i = blockIdx.x * blockDim.x + threadIdx.x;
    if (i < N_NODES) {
        int v = g_excl[i] + g_bsum[i >> 10];
        g_rowptr[i] = v;
        g_cnt[i] = v;
    }
    if (i == 0) g_rowptr[N_NODES] = N_EDGES;
}

__global__ void fill_kernel(const int* __restrict__ src, const int* __restrict__ dst) {
    int e = blockIdx.x * blockDim.x + threadIdx.x;
    if (e < N_EDGES) {
        int d = dst[e];
        int p = atomicAdd(&g_cnt[d], 1);
        g_csrsrc[p] = src[e];
    }
}

// ---------------- GIN aggregation (bf16 in, fp32 accumulate, bf16 out) ----------
__device__ __forceinline__ void add4(float* a, uint2 v) {
    __nv_bfloat162 p0 = *(__nv_bfloat162*)&v.x;
    __nv_bfloat162 p1 = *(__nv_bfloat162*)&v.y;
    float2 f0 = __bfloat1622float2(p0), f1 = __bfloat1622float2(p1);
    a[0] += f0.x; a[1] += f0.y; a[2] += f1.x; a[3] += f1.y;
}

__device__ __forceinline__ uint2 pack4(const float* a) {
    uint2 r;
    __nv_bfloat162 p0 = __floats2bfloat162_rn(a[0], a[1]);
    __nv_bfloat162 p1 = __floats2bfloat162_rn(a[2], a[3]);
    r.x = *(uint32_t*)&p0; r.y = *(uint32_t*)&p1;
    return r;
}

// F=64: warp per node, one bfloat162 (4B) per lane
__global__ void agg64_kernel(const __nv_bfloat16* __restrict__ X, const float* __restrict__ epsp,
                             __nv_bfloat16* __restrict__ out) {
    int w = (blockIdx.x * blockDim.x + threadIdx.x) >> 5;
    int lane = threadIdx.x & 31;
    if (w >= N_NODES) return;
    float2 acc = make_float2(0.f, 0.f);
    int beg = g_rowptr[w], end = g_rowptr[w + 1];
    for (int e = beg; e < end; e++) {
        int s = g_csrsrc[e];
        float2 f = __bfloat1622float2(__ldg((const __nv_bfloat162*)(X + (size_t)s * F_IN) + lane));
        acc.x += f.x; acc.y += f.y;
    }
    float ep = 1.f + *epsp;
    float2 xi = __bfloat1622float2(*((const __nv_bfloat162*)(X + (size_t)w * F_IN) + lane));
    *(((__nv_bfloat162*)(out + (size_t)w * F_IN)) + lane) =
        __floats2bfloat162_rn(ep * xi.x + acc.x, ep * xi.y + acc.y);
}

// F=200: warp per node; 50 uint2 (8B) per row: lane gets idx lane, and lane+32 (lane<18)
__global__ void agg200_kernel(const __nv_bfloat16* __restrict__ X, const float* __restrict__ epsp,
                              __nv_bfloat16* __restrict__ out) {
    int w = (blockIdx.x * blockDim.x + threadIdx.x) >> 5;
    int lane = threadIdx.x & 31;
    if (w >= N_NODES) return;
    float a0[4] = {0.f, 0.f, 0.f, 0.f};
    float a1[4] = {0.f, 0.f, 0.f, 0.f};
    bool has2 = lane < 18;
    int beg = g_rowptr[w], end = g_rowptr[w + 1];
    for (int e = beg; e < end; e++) {
        int s = g_csrsrc[e];
        const uint2* xs = (const uint2*)(X + (size_t)s * HDIM);
        add4(a0, __ldg(xs + lane));
        if (has2) add4(a1, __ldg(xs + lane + 32));
    }
    float ep = 1.f + *epsp;
    const uint2* xi = (const uint2*)(X + (size_t)w * HDIM);
    uint2* o = (uint2*)(out + (size_t)w * HDIM);
    {
        float s0[4];
        uint2 xv = xi[lane];
        float t[4] = {0.f, 0.f, 0.f, 0.f};
        add4(t, xv);
        for (int j = 0; j < 4; j++) s0[j] = ep * t[j] + a0[j];
        o[lane] = pack4(s0);
    }
    if (has2) {
        float s1[4];
        uint2 xv = xi[lane + 32];
        float t[4] = {0.f, 0.f, 0.f, 0.f};
        add4(t, xv);
        for (int j = 0; j < 4; j++) s1[j] = ep * t[j] + a1[j];
        o[lane + 32] = pack4(s1);
    }
}

// ---------------- bf16 tensor-core GEMM: C[M,N] = epi(A[M,K] @ B[K,N]) --------------
__device__ __forceinline__ uint32_t s2u(const void* p) {
    return (uint32_t)__cvta_generic_to_shared(p);
}

__device__ __forceinline__ void cpasync16(uint32_t dst, const void* src, int bytes) {
    asm volatile("cp.async.cg.shared.global [%0], [%1], 16, %2;\n"
                 :: "r"(dst), "l"(src), "r"(bytes));
}

__device__ __forceinline__ void mma_bf16(float* c, const uint32_t* a, uint32_t b0, uint32_t b1) {
    asm volatile(
        "mma.sync.aligned.m16n8k16.row.col.f32.bf16.bf16.f32 "
        "{%0,%1,%2,%3},{%4,%5,%6,%7},{%8,%9},{%0,%1,%2,%3};"
        : "+f"(c[0]), "+f"(c[1]), "+f"(c[2]), "+f"(c[3])
        : "r"(a[0]), "r"(a[1]), "r"(a[2]), "r"(a[3]), "r"(b0), "r"(b1));
}

// EPI 0: relu(acc + bias); EPI 1: bn(relu(acc + bias))
template <int EPI, bool OUT_BF16>
__global__ __launch_bounds__(256) void gemm_bf16_kernel(
    const __nv_bfloat16* __restrict__ A, const __nv_bfloat16* __restrict__ B,
    const float* __restrict__ bias,
    const float* __restrict__ gamma, const float* __restrict__ beta,
    const float* __restrict__ mean, const float* __restrict__ var,
    void* __restrict__ Cv, int M, int K, int N) {
    const int AS_STRIDE = 24;   // bf16 units; 48B rows -> conflict-free LDSM
    const int BS_STRIDE = 136;  // 272B rows == 16 mod 128 -> conflict-free LDSM
    __shared__ __align__(16) __nv_bfloat16 As[2][128 * AS_STRIDE];
    __shared__ __align__(16) __nv_bfloat16 Bs[2][16 * BS_STRIDE];

    int tid = threadIdx.x;
    int lane = tid & 31, wid = tid >> 5;
    int warp_m = wid & 3, warp_n = wid >> 2;  // 4x2 warp grid; warp tile 32x64
    int row0 = blockIdx.x * 128, col0 = blockIdx.y * 128;
    int g = lane >> 2, t4 = lane & 3;

    float acc[2][8][4];
#pragma unroll
    for (int mt = 0; mt < 2; mt++)
#pragma unroll
        for (int nt = 0; nt < 8; nt++)
#pragma unroll
            for (int i = 0; i < 4; i++) acc[mt][nt][i] = 0.f;

    // loaders: A -> 256 threads x 16B (128 rows x 2 halves); B -> 16 rows x 16 cols of 16B
    int la_m = tid >> 1, la_kh = tid & 1;
    int lb_r = tid >> 4, lb_c = (tid & 15) * 8;
    int ar = row0 + la_m;
    const __nv_bfloat16* aRow = A + (size_t)(ar < M ? ar : 0) * K;
    uint32_t aDst[2], bDst[2];
#pragma unroll
    for (int s = 0; s < 2; s++) {
        aDst[s] = s2u(&As[s][la_m * AS_STRIDE + la_kh * 8]);
        bDst[s] = s2u(&Bs[s][lb_r * BS_STRIDE + lb_c]);
    }
    bool bcol_ok = (col0 + lb_c) < N;

    int nk = (K + 15) / 16;

#define LOADSTAGE(kt, s)                                                        \
    {                                                                           \
        int k0 = (kt) * 16;                                                     \
        int ka = k0 + la_kh * 8;                                                \
        int abytes = (ar < M && ka < K) ? 16 : 0;                               \
        cpasync16(aDst[s], aRow + (abytes ? ka : 0), abytes);                   \
        int kb = k0 + lb_r;                                                     \
        int bbytes = (kb < K && bcol_ok) ? 16 : 0;                              \
        cpasync16(bDst[s], B + (size_t)(bbytes ? kb : 0) * N + col0 + lb_c,     \
                  bbytes);                                                      \
    }

    LOADSTAGE(0, 0);
    asm volatile("cp.async.commit_group;\n");

    for (int kt = 0; kt < nk; kt++) {
        if (kt + 1 < nk) {
            LOADSTAGE(kt + 1, (kt + 1) & 1);
            asm volatile("cp.async.commit_group;\n");
            asm volatile("cp.async.wait_group 1;\n");
        } else {
            asm volatile("cp.async.wait_group 0;\n");
        }
        __syncthreads();

        int s = kt & 1;
        uint32_t af[2][4];
        uint32_t abase = s2u(&As[s][0]);
        int arow_f = warp_m * 32 + (lane & 15);
#pragma unroll
        for (int mt = 0; mt < 2; mt++) {
            uint32_t addr = abase + (uint32_t)((arow_f + mt * 16) * (AS_STRIDE * 2) + (lane >> 4) * 16);
            asm volatile("ldmatrix.sync.aligned.m8n8.x4.shared.b16 {%0,%1,%2,%3}, [%4];"
                         : "=r"(af[mt][0]), "=r"(af[mt][1]), "=r"(af[mt][2]), "=r"(af[mt][3])
                         : "r"(addr));
        }
        uint32_t bb[4][4];
        uint32_t bbase = s2u(&Bs[s][0]);
#pragma unroll
        for (int p = 0; p < 4; p++) {
            uint32_t addr = bbase + (uint32_t)((lane & 15) * (BS_STRIDE * 2) +
                                               (warp_n * 64 + p * 16 + (lane >> 4) * 8) * 2);
            asm volatile("ldmatrix.sync.aligned.m8n8.x4.trans.shared.b16 {%0,%1,%2,%3}, [%4];"
                         : "=r"(bb[p][0]), "=r"(bb[p][1]), "=r"(bb[p][2]), "=r"(bb[p][3])
                         : "r"(addr));
        }
#pragma unroll
        for (int nt = 0; nt < 8; nt++) {
            uint32_t b0 = bb[nt >> 1][(nt & 1) * 2];
            uint32_t b1 = bb[nt >> 1][(nt & 1) * 2 + 1];
            mma_bf16(acc[0][nt], af[0], b0, b1);
            mma_bf16(acc[1][nt], af[1], b0, b1);
        }
        __syncthreads();
    }
#undef LOADSTAGE

    // epilogue; per mma: c0:(g, 2t4) c1:(g, 2t4+1) c2:(g+8, 2t4) c3:(g+8, 2t4+1)
#pragma unroll
    for (int nt = 0; nt < 8; nt++) {
        int col = col0 + warp_n * 64 + nt * 8 + 2 * t4;  // even; N even -> col+1 valid
        if (col >= N) continue;
        float bi0 = bias[col], bi1 = bias[col + 1];
        float s0 = 1.f, s1 = 1.f, o0 = 0.f, o1 = 0.f;
        if (EPI == 1) {
            s0 = rsqrtf(var[col] + BN_EPS) * gamma[col];
            s1 = rsqrtf(var[col + 1] + BN_EPS) * gamma[col + 1];
            o0 = beta[col] - mean[col] * s0;
            o1 = beta[col + 1] - mean[col + 1] * s1;
        }
#pragma unroll
        for (int mt = 0; mt < 2; mt++) {
#pragma unroll
            for (int h = 0; h < 2; h++) {
                int r = row0 + warp_m * 32 + mt * 16 + g + h * 8;
                if (r >= M) continue;
                float v0 = fmaxf(acc[mt][nt][2 * h + 0] + bi0, 0.f);
                float v1 = fmaxf(acc[mt][nt][2 * h + 1] + bi1, 0.f);
                if (EPI == 1) { v0 = v0 * s0 + o0; v1 = v1 * s1 + o1; }
                if (OUT_BF16) {
                    *(__nv_bfloat162*)((__nv_bfloat16*)Cv + (size_t)r * N + col) =
                        __floats2bfloat162_rn(v0, v1);
                } else {
                    *(float2*)((float*)Cv + (size_t)r * N + col) = make_float2(v0, v1);
                }
            }
        }
    }
}

// ---------------- pooling ----------------
__global__ void graph_bounds_kernel(const int* __restrict__ batch) {
    int g = blockIdx.x * blockDim.x + threadIdx.x;
    if (g > N_GRAPHS) return;
    int lo = 0, hi = N_NODES;
    while (lo < hi) {
        int mid = (lo + hi) >> 1;
        if (batch[mid] < g) lo = mid + 1; else hi = mid;
    }
    g_bounds[g] = lo;
}

__global__ void pool_kernel() {
    int g = blockIdx.x;
    int f = threadIdx.x;
    if (f >= HDIM) return;
    int beg = g_bounds[g], end = g_bounds[g + 1];
    float s = 0.f, m = -INFINITY;
    for (int i = beg; i < end; i++) {
        float v = g_h2[(size_t)i * HDIM + f];
        s += v;
        m = fmaxf(m, v);
    }
    g_pooled[g * (2 * HDIM) + f] = s;
    g_pooled[g * (2 * HDIM) + HDIM + f] = m;
}

// ---------------- FC + log_softmax ----------------
__global__ void fc_kernel(const float* __restrict__ Wfc, const float* __restrict__ bfc,
                          float* __restrict__ out) {
    int w = (blockIdx.x * blockDim.x + threadIdx.x) >> 5;
    int lane = threadIdx.x & 31;
    if (w >= N_GRAPHS) return;
    float l0 = 0.f, l1 = 0.f;
    const float* p = &g_pooled[w * (2 * HDIM)];
    for (int k = lane; k < 2 * HDIM; k += 32) {
        float pv = p[k];
        l0 += pv * Wfc[k * 2 + 0];
        l1 += pv * Wfc[k * 2 + 1];
    }
#pragma unroll
    for (int off = 16; off; off >>= 1) {
        l0 += __shfl_down_sync(0xFFFFFFFFu, l0, off);
        l1 += __shfl_down_sync(0xFFFFFFFFu, l1, off);
    }
    if (lane == 0) {
        l0 += bfc[0];
        l1 += bfc[1];
        float m = fmaxf(l0, l1);
        float lse = m + logf(expf(l0 - m) + expf(l1 - m));
        out[w * 2 + 0] = l0 - lse;
        out[w * 2 + 1] = l1 - lse;
    }
}

// ---------------- launch ----------------
extern "C" void kernel_launch(void* const* d_in, const int* in_sizes, int n_in,
                              void* d_out, int out_size) {
    const float* x    = (const float*)d_in[0];
    const int*   ei   = (const int*)d_in[1];
    const int*   batch = (const int*)d_in[2];
    const float* eps1 = (const float*)d_in[3];
    const float* W1a  = (const float*)d_in[4];
    const float* b1a  = (const float*)d_in[5];
    const float* W1b  = (const float*)d_in[6];
    const float* b1b  = (const float*)d_in[7];
    const float* bn1g = (const float*)d_in[8];
    const float* bn1b = (const float*)d_in[9];
    const float* bn1m = (const float*)d_in[10];
    const float* bn1v = (const float*)d_in[11];
    const float* eps2 = (const float*)d_in[12];
    const float* W2a  = (const float*)d_in[13];
    const float* b2a  = (const float*)d_in[14];
    const float* W2b  = (const float*)d_in[15];
    const float* b2b  = (const float*)d_in[16];
    const float* bn2g = (const float*)d_in[17];
    const float* bn2b = (const float*)d_in[18];
    const float* bn2m = (const float*)d_in[19];
    const float* bn2v = (const float*)d_in[20];
    const float* Wfc  = (const float*)d_in[21];
    const float* bfc  = (const float*)d_in[22];
    float* out = (float*)d_out;

    const int* src = ei;
    const int* dst = ei + N_EDGES;

    __nv_bfloat16 *xb, *hin1, *tb, *h1, *hin2, *w1a, *w1b, *w2a, *w2b;
    float* h2;
    cudaGetSymbolAddress((void**)&xb,   g_xb);
    cudaGetSymbolAddress((void**)&hin1, g_hin1);
    cudaGetSymbolAddress((void**)&tb,   g_tb);
    cudaGetSymbolAddress((void**)&h1,   g_h1);
    cudaGetSymbolAddress((void**)&hin2, g_hin2);
    cudaGetSymbolAddress((void**)&h2,   g_h2);
    cudaGetSymbolAddress((void**)&w1a,  g_w1a);
    cudaGetSymbolAddress((void**)&w1b,  g_w1b);
    cudaGetSymbolAddress((void**)&w2a,  g_w2a);
    cudaGetSymbolAddress((void**)&w2b,  g_w2b);

    const int TPB = 256;
    int nbNodes = (N_NODES + TPB - 1) / TPB;
    int nbEdges = (N_EDGES + TPB - 1) / TPB;
    int nbScan  = (N_NODES + 1023) / 1024;
    int nbWarpNodes = (N_NODES * 32 + TPB - 1) / TPB;

    // conversions (x + weights)
    convf2b_kernel<<<(N_NODES * F_IN + 511) / 512, 512>>>(x, xb, N_NODES * F_IN);
    convf2b_kernel<<<(F_IN * HDIM + 255) / 256, 256>>>(W1a, w1a, F_IN * HDIM);
    convf2b_kernel<<<(HDIM * HDIM + 255) / 256, 256>>>(W1b, w1b, HDIM * HDIM);
    convf2b_kernel<<<(HDIM * HDIM + 255) / 256, 256>>>(W2a, w2a, HDIM * HDIM);
    convf2b_kernel<<<(HDIM * HDIM + 255) / 256, 256>>>(W2b, w2b, HDIM * HDIM);

    // CSR build (reused by both layers)
    zero_deg_kernel<<<nbNodes, TPB>>>();
    hist_kernel<<<nbEdges, TPB>>>(dst);
    scan_block_kernel<<<nbScan, 1024>>>();
    scan_sums_kernel<<<1, 32>>>(nbScan);
    scan_finish_kernel<<<nbNodes, TPB>>>();
    fill_kernel<<<nbEdges, TPB>>>(src, dst);

    dim3 gemm_grid((N_NODES + 127) / 128, (HDIM + 127) / 128);  // 782 x 2

    // Layer 1
    agg64_kernel<<<nbWarpNodes, TPB>>>(xb, eps1, hin1);
    gemm_bf16_kernel<0, true><<<gemm_grid, 256>>>(hin1, w1a, b1a, nullptr, nullptr, nullptr,
                                                  nullptr, tb, N_NODES, F_IN, HDIM);
    gemm_bf16_kernel<1, true><<<gemm_grid, 256>>>(tb, w1b, b1b, bn1g, bn1b, bn1m, bn1v,
                                                  h1, N_NODES, HDIM, HDIM);

    // Layer 2
    agg200_kernel<<<nbWarpNodes, TPB>>>(h1, eps2, hin2);
    gemm_bf16_kernel<0, true><<<gemm_grid, 256>>>(hin2, w2a, b2a, nullptr, nullptr, nullptr,
                                                  nullptr, tb, N_NODES, HDIM, HDIM);
    gemm_bf16_kernel<1, false><<<gemm_grid, 256>>>(tb, w2b, b2b, bn2g, bn2b, bn2m, bn2v,
                                                   h2, N_NODES, HDIM, HDIM);

    // Pooling + FC + log_softmax
    graph_bounds_kernel<<<3, 256>>>(batch);
    pool_kernel<<<N_GRAPHS, 256>>>();
    fc_kernel<<<(N_GRAPHS * 32 + TPB - 1) / TPB, TPB>>>(Wfc, bfc, out);
}